// round 10
// baseline (speedup 1.0000x reference)
#include <cuda_runtime.h>
#include <cuda_bf16.h>
#include <cstdint>
#include <math.h>

// Problem constants
static constexpr int Bz   = 32;
static constexpr int INC  = 64;
static constexpr int HIDN = 128;
static constexpr int Gg   = 384;
static constexpr int RR   = 63;
static constexpr int CELLS = RR * RR; // 3969
static constexpr int NCTA_D = 36;     // CTAs per direction (4 kq x 9)
static constexpr int NCTAS  = 144;

// Scratch (allocation-free: __device__ globals)
__device__ float g_gx [(size_t)4 * CELLS * Bz * Gg];    // gx = x@Wx + b   [d][p][q][b][g]
__device__ float g_h  [(size_t)4 * CELLS * Bz * HIDN];  // hidden states   [d][p][q][b][k]
__device__ float g_Whi[(size_t)4 * 256 * Gg];           // trunc13([Wh;Wh2])  [d][k'][g]
__device__ float g_Wlo[(size_t)4 * 256 * Gg];           // residual           [d][k'][g]
__device__ int          g_bar_count[4];
__device__ volatile int g_bar_gen[4];

// ---------------------------------------------------------------------------
__device__ __forceinline__ unsigned smem_u32(const void* p) {
    return (unsigned)__cvta_generic_to_shared(p);
}
#define CPA16(dst, src) asm volatile("cp.async.cg.shared.global [%0], [%1], 16;" :: "r"(dst), "l"(src))
#define CPC()  asm volatile("cp.async.commit_group;")
#define CPW0() asm volatile("cp.async.wait_group 0;")
#define CPW1() asm volatile("cp.async.wait_group 1;")

#define MMA_TF32(D, a0, a1, a2, a3, bb0, bb1)                                   \
    asm volatile("mma.sync.aligned.m16n8k8.row.col.f32.tf32.tf32.f32 "          \
                 "{%0,%1,%2,%3}, {%4,%5,%6,%7}, {%8,%9}, {%0,%1,%2,%3};"        \
                 : "+f"(D[0]), "+f"(D[1]), "+f"(D[2]), "+f"(D[3])               \
                 : "r"(a0), "r"(a1), "r"(a2), "r"(a3), "r"(bb0), "r"(bb1))

__device__ __forceinline__ float sigf(float x)  { return 1.f / (1.f + __expf(-x)); }
__device__ __forceinline__ float tanhf_fast(float x) {
    float e = __expf(2.f * x);
    return (e - 1.f) / (e + 1.f);
}
__device__ __forceinline__ float trunc_tf32(float x) {
    return __uint_as_float(__float_as_uint(x) & 0xFFFFE000u);
}

// ---------------------------------------------------------------------------
__global__ void fill_ones_kernel(float4* out, int n4) {
    int i = blockIdx.x * 256 + threadIdx.x;
    if (i < n4) out[i] = make_float4(1.f, 1.f, 1.f, 1.f);
}

__global__ void reset_kernel() {
    for (int d = 0; d < 4; d++) { g_bar_count[d] = 0; g_bar_gen[d] = 0; }
}

// ---------------------------------------------------------------------------
// Split [Wh;Wh2] into tf32 hi/lo pair. 4*256*384 elems = 768 x 512.
__global__ void wsplit_kernel(const float* __restrict__ Wh,
                              const float* __restrict__ Wh2) {
    int i = blockIdx.x * 512 + threadIdx.x;
    int d = i / (256 * Gg);
    int r = (i / Gg) % 256;
    int g = i % Gg;
    float w = (r < 128) ? Wh [(size_t)d * 128 * Gg + (size_t)r * Gg + g]
                        : Wh2[(size_t)d * 128 * Gg + (size_t)(r - 128) * Gg + g];
    float hi = trunc_tf32(w);
    g_Whi[i] = hi;
    g_Wlo[i] = w - hi;
}

// ---------------------------------------------------------------------------
// gx precompute (fp32 FFMA — fully parallel, off the critical path)
static constexpr int GX_SMEM = (32 * 68 + 2 * 16 * Gg) * 4;

__global__ void __launch_bounds__(256) gx_kernel(const float* __restrict__ x,
                                                 const float* __restrict__ Wx,
                                                 const float* __restrict__ bias) {
    extern __shared__ float sm[];
    float* Xs  = sm;
    float* Wsb = sm + 32 * 68;

    const int cellpq = blockIdx.x;
    const int d      = blockIdx.y;
    const int p = cellpq / RR, q = cellpq % RR;
    const int ix = (d & 1) ? (62 - p) : p;
    const int jx = (d & 2) ? (62 - q) : q;
    const int t = threadIdx.x;
    const int tx = t & 15, ty = t >> 4;
    const int b0 = ty * 2;
    const float* Wd = Wx + (size_t)d * INC * Gg;

    auto stageW = [&](int kb, int buf) {
        float* W = Wsb + buf * (16 * Gg);
        for (int f = t; f < 16 * 96; f += 256) {
            int kk = f / 96, x16 = f % 96;
            CPA16(smem_u32(W + kk * Gg + x16 * 4),
                  Wd + (size_t)(kb * 16 + kk) * Gg + x16 * 4);
        }
    };
    stageW(0, 0); CPC();
    stageW(1, 1); CPC();

    for (int m = t; m < Bz * INC; m += 256) {
        int b_ = m >> 6, c = m & 63;
        Xs[b_ * 68 + c] = x[((size_t)(b_ * INC + c) << 12) + (ix << 6) + jx];
    }

    float acc[6][4][2];
    const float* bb = bias + d * Gg;
#pragma unroll
    for (int c = 0; c < 6; c++) {
        float4 v = *(const float4*)(bb + c * 64 + tx * 4);
        acc[c][0][0] = v.x; acc[c][0][1] = v.x;
        acc[c][1][0] = v.y; acc[c][1][1] = v.y;
        acc[c][2][0] = v.z; acc[c][2][1] = v.z;
        acc[c][3][0] = v.w; acc[c][3][1] = v.w;
    }

#pragma unroll 1
    for (int kb = 0; kb < 4; kb++) {
        if (kb < 3) { CPW1(); } else { CPW0(); }
        __syncthreads();
        const float* W = Wsb + (kb & 1) * (16 * Gg);
        const float* Arow = Xs + b0 * 68 + kb * 16;
#pragma unroll 8
        for (int kk = 0; kk < 16; kk++) {
            float a0 = Arow[kk];
            float a1 = Arow[68 + kk];
            const float* wr = W + kk * Gg + tx * 4;
#pragma unroll
            for (int c = 0; c < 6; c++) {
                float4 w = *(const float4*)(wr + c * 64);
                acc[c][0][0] += a0 * w.x; acc[c][0][1] += a1 * w.x;
                acc[c][1][0] += a0 * w.y; acc[c][1][1] += a1 * w.y;
                acc[c][2][0] += a0 * w.z; acc[c][2][1] += a1 * w.z;
                acc[c][3][0] += a0 * w.w; acc[c][3][1] += a1 * w.w;
            }
        }
        __syncthreads();
        if (kb < 2) { stageW(kb + 2, kb & 1); CPC(); }
    }

    float* gp = g_gx + ((size_t)(d * CELLS + cellpq) * Bz + b0) * Gg;
#pragma unroll
    for (int c = 0; c < 6; c++) {
#pragma unroll
        for (int b2 = 0; b2 < 2; b2++) {
            *(float4*)(gp + (size_t)b2 * Gg + c * 64 + tx * 4) =
                make_float4(acc[c][0][b2], acc[c][1][b2], acc[c][2][b2], acc[c][3][b2]);
        }
    }
}

// ---------------------------------------------------------------------------
// Persistent wavefront scan. CTA = (d, kq, j), 512 threads / 16 warps.
// Weights stationary in SMEM (Whi fp32 + Wlo bf16, rows padded to 104 words).
// Per task (pair of diagonal cells, M=64): 3xTF32 mma.sync, warp (mt, part)
// owns m16 tile mt and n8 column group part for all 3 gates.
static constexpr int PAD_W2 = 104;                    // 96 cols + 8 pad
static constexpr int PAD_A2 = 260;                    // 256 cols + 4 pad
static constexpr int PERSIST_SMEM =
    256 * PAD_W2 * 4 + 256 * PAD_W2 * 2 + 64 * PAD_A2 * 4;   // 226304 B

__device__ __forceinline__ void grid_barrier_d(int d, int gen) {
    __syncthreads();
    if (threadIdx.x == 0) {
        __threadfence();
        if (atomicAdd(&g_bar_count[d], 1) == NCTA_D - 1) {
            g_bar_count[d] = 0;
            __threadfence();
            g_bar_gen[d] = gen;
        } else {
            while (g_bar_gen[d] < gen) { __nanosleep(32); }
            __threadfence();
        }
    }
    __syncthreads();
}

__global__ void __launch_bounds__(512, 1) scan_persist_kernel(float* __restrict__ out) {
    extern __shared__ float sm[];
    float* Wh_s = sm;                                            // [256][104] fp32
    __nv_bfloat16* Wl_s = (__nv_bfloat16*)(sm + 256 * PAD_W2);   // [256][104] bf16
    float* A = sm + 256 * PAD_W2 + 256 * PAD_W2 / 2;             // [64][260]  fp32

    const int cta = blockIdx.x;
    const int d  = cta / 36;
    const int kq = (cta / 9) % 4;
    const int j  = cta % 9;
    const int t  = threadIdx.x;
    const int w = t >> 5, lane = t & 31;
    const int gi = lane >> 2, ci = lane & 3;
    const int mt = w >> 2;      // m16 tile (0..3) within M=64
    const int part = w & 3;     // n8 column group within each gate's 32 cols

    // ---- one-time weight staging: cols c = gate*32 + koff ----
    for (int idx = t; idx < 256 * 96; idx += 512) {
        int k = idx / 96, c = idx % 96;
        int gate = c >> 5, koff = c & 31;
        size_t gsrc = ((size_t)d * 256 + k) * Gg + gate * 128 + kq * 32 + koff;
        Wh_s[k * PAD_W2 + c] = g_Whi[gsrc];
        Wl_s[k * PAD_W2 + c] = __float2bfloat16(g_Wlo[gsrc]);
    }
    __syncthreads();

    for (int s = 0; s < 2 * RR - 1; s++) {
        const int qlo = (s - (RR - 1) > 0) ? (s - (RR - 1)) : 0;
        const int qhi = (s < RR - 1) ? s : (RR - 1);
        const int npairs = (qhi - qlo + 2) >> 1;

        for (int pi = j; pi < npairs; pi += 9) {
            const int q0 = qlo + 2 * pi;
            const int q1 = q0 + 1;
            const bool c1ok = (q1 <= qhi);
            const int p0 = s - q0;
            const int p1 = s - q1;
            const size_t cell0 = (size_t)d * CELLS + (size_t)p0 * RR + q0;
            const size_t cell1 = (size_t)d * CELLS + (size_t)p1 * RR + q1;

            // ---- stage A: rows 0-31 cell0, 32-63 cell1; cols [0,128)=h_up,
            //      [128,256)=h_left. cp.async.cg (L1-bypass: cross-CTA h).
            {
                const float* hu0 = (p0 > 0) ? g_h + (cell0 - RR) * (Bz * HIDN) : nullptr;
                const float* hl0 = (q0 > 0) ? g_h + (cell0 - 1)  * (Bz * HIDN) : nullptr;
                const float* hu1 = (c1ok && p1 > 0) ? g_h + (cell1 - RR) * (Bz * HIDN) : nullptr;
                const float* hl1 = (c1ok && q1 > 0) ? g_h + (cell1 - 1)  * (Bz * HIDN) : nullptr;
                for (int f = t; f < 4096; f += 512) {
                    int row = f >> 6;
                    int col = (f & 63) * 4;
                    const float* src;
                    if (row < 32)
                        src = (col < 128) ? (hu0 ? hu0 + row * 128 + col : nullptr)
                                          : (hl0 ? hl0 + row * 128 + (col - 128) : nullptr);
                    else
                        src = (col < 128) ? (hu1 ? hu1 + (row - 32) * 128 + col : nullptr)
                                          : (hl1 ? hl1 + (row - 32) * 128 + (col - 128) : nullptr);
                    float* dst = A + row * PAD_A2 + col;
                    if (src) { CPA16(smem_u32(dst), src); }
                    else     { *(float4*)dst = make_float4(0.f, 0.f, 0.f, 0.f); }
                }
                CPC(); CPW0();
                __syncthreads();
            }

            // ---- 3xTF32 MMA mainloop over K=256 (32 k-steps of 8) ----
            float acc[3][4];
#pragma unroll
            for (int g = 0; g < 3; g++)
#pragma unroll
                for (int v = 0; v < 4; v++) acc[g][v] = 0.f;

            const int cb0 = part * 8 + gi;          // B col within each gate's 32
            const float* Arow0 = A + (mt * 16 + gi) * PAD_A2 + ci;

#pragma unroll 2
            for (int k8 = 0; k8 < 32; k8++) {
                const int kr = k8 * 8;
                unsigned bh0[3], bh1[3], bl0[3], bl1[3];
#pragma unroll
                for (int g = 0; g < 3; g++) {
                    const int c = g * 32 + cb0;
                    bh0[g] = __float_as_uint(Wh_s[(kr + ci) * PAD_W2 + c]);
                    bh1[g] = __float_as_uint(Wh_s[(kr + ci + 4) * PAD_W2 + c]);
                    bl0[g] = __float_as_uint(__bfloat162float(Wl_s[(kr + ci) * PAD_W2 + c]));
                    bl1[g] = __float_as_uint(__bfloat162float(Wl_s[(kr + ci + 4) * PAD_W2 + c]));
                }
                const float* Ab = Arow0 + kr;
                float a0 = Ab[0], a1 = Ab[8 * PAD_A2];
                float a2 = Ab[4], a3 = Ab[8 * PAD_A2 + 4];
                unsigned ua0 = __float_as_uint(a0), ua1 = __float_as_uint(a1);
                unsigned ua2 = __float_as_uint(a2), ua3 = __float_as_uint(a3);
                unsigned ul0 = __float_as_uint(a0 - trunc_tf32(a0));
                unsigned ul1 = __float_as_uint(a1 - trunc_tf32(a1));
                unsigned ul2 = __float_as_uint(a2 - trunc_tf32(a2));
                unsigned ul3 = __float_as_uint(a3 - trunc_tf32(a3));
#pragma unroll
                for (int g = 0; g < 3; g++) {
                    MMA_TF32(acc[g], ua0, ua1, ua2, ua3, bh0[g], bh1[g]);  // hi*hi
                    MMA_TF32(acc[g], ua0, ua1, ua2, ua3, bl0[g], bl1[g]);  // hi*lo
                    MMA_TF32(acc[g], ul0, ul1, ul2, ul3, bh0[g], bh1[g]);  // lo*hi
                }
            }

            // ---- GRU epilogue: warp (mt, part); mt 0,1 -> cell0; 2,3 -> cell1
            const int cIdx = mt >> 1;
            if (!(cIdx == 1 && !c1ok)) {
                const size_t cell = cIdx ? cell1 : cell0;
                const int p = cIdx ? p1 : p0;
                const int q = cIdx ? q1 : q0;
                const int oi = (d & 1) ? (63 - p) : p;
                const int oj = (d & 2) ? (63 - q) : q;
                float* hdst = g_h + cell * (Bz * HIDN);
#pragma unroll
                for (int half = 0; half < 2; half++) {
                    const int row = mt * 16 + gi + half * 8;   // A row (0..63)
                    const int b = row & 31;                    // batch
                    const float* gxc = g_gx + (cell * Bz + b) * Gg;
#pragma unroll
                    for (int c = 0; c < 2; c++) {
                        const int k = kq * 32 + part * 8 + 2 * ci + c;
                        float rr_ = sigf(acc[0][half * 2 + c] + __ldcg(gxc + k));
                        float zz  = sigf(acc[1][half * 2 + c] + __ldcg(gxc + 128 + k));
                        float nn  = tanhf_fast(__ldcg(gxc + 256 + k)
                                               + rr_ * acc[2][half * 2 + c]);
                        float hu  = A[row * PAD_A2 + k];
                        float hl  = A[row * PAD_A2 + 128 + k];
                        float h   = (1.f - zz) * nn + zz * 0.5f * (hu + hl);
                        hdst[b * 128 + k] = h;
                        out[((size_t)(b * 128 + k) * 4 + d) * 4096
                            + (size_t)oi * 64 + oj] = h;
                    }
                }
            }
            __syncthreads();   // protect A before next pair overwrites it
        }

        grid_barrier_d(d, s + 1);
    }
}

// ---------------------------------------------------------------------------
extern "C" void kernel_launch(void* const* d_in, const int* in_sizes, int n_in,
                              void* d_out, int out_size) {
    const float* x    = (const float*)d_in[0];
    const float* Wx   = (const float*)d_in[1];
    const float* Wh   = (const float*)d_in[2];
    const float* Wh2  = (const float*)d_in[3];
    const float* bias = (const float*)d_in[4];
    float* out = (float*)d_out;

    cudaFuncSetAttribute(gx_kernel, cudaFuncAttributeMaxDynamicSharedMemorySize, GX_SMEM);
    cudaFuncSetAttribute(scan_persist_kernel,
                         cudaFuncAttributeMaxDynamicSharedMemorySize, PERSIST_SMEM);

    // 1) independent prep
    int n4 = out_size / 4;
    fill_ones_kernel<<<(n4 + 255) / 256, 256>>>((float4*)d_out, n4);
    wsplit_kernel<<<768, 512>>>(Wh, Wh2);
    reset_kernel<<<1, 1>>>();

    // 2) gx precompute
    {
        dim3 grid(CELLS, 4);
        gx_kernel<<<grid, 256, GX_SMEM>>>(x, Wx, bias);
    }

    // 3) persistent wavefront scan (single launch; weights SMEM-resident)
    scan_persist_kernel<<<NCTAS, 512, PERSIST_SMEM>>>(out);
}

// round 11
// speedup vs baseline: 1.4584x; 1.4584x over previous
#include <cuda_runtime.h>
#include <cuda_bf16.h>
#include <cstdint>
#include <math.h>

// Problem constants
static constexpr int Bz   = 32;
static constexpr int INC  = 64;
static constexpr int HIDN = 128;
static constexpr int Gg   = 384;
static constexpr int RR   = 63;
static constexpr int CELLS = RR * RR; // 3969
static constexpr int NCTA_D = 36;     // CTAs per direction (4 kq x 9)
static constexpr int NCTAS  = 144;

// Scratch (allocation-free: __device__ globals)
__device__ float g_gx [(size_t)4 * CELLS * Bz * Gg];    // gx = x@Wx + b   [d][p][q][b][g]
__device__ float g_h  [(size_t)4 * CELLS * Bz * HIDN];  // hidden states   [d][p][q][b][k]
__device__ uint32_t g_Wph[(size_t)4 * 128 * Gg];        // bf16x2 hi of [Wh;Wh2], k-pair packed [d][kp][g]
__device__ uint32_t g_Wpm[(size_t)4 * 128 * Gg];        // bf16x2 mid residual                 [d][kp][g]
__device__ int          g_bar_count[4];
__device__ volatile int g_bar_gen[4];

// ---------------------------------------------------------------------------
__device__ __forceinline__ unsigned smem_u32(const void* p) {
    return (unsigned)__cvta_generic_to_shared(p);
}
#define CPA16(dst, src) asm volatile("cp.async.cg.shared.global [%0], [%1], 16;" :: "r"(dst), "l"(src))
#define CPC()  asm volatile("cp.async.commit_group;")
#define CPW0() asm volatile("cp.async.wait_group 0;")
#define CPW1() asm volatile("cp.async.wait_group 1;")

#define MMA_BF16(D, a0, a1, a2, a3, bb0, bb1)                                   \
    asm volatile("mma.sync.aligned.m16n8k16.row.col.f32.bf16.bf16.f32 "         \
                 "{%0,%1,%2,%3}, {%4,%5,%6,%7}, {%8,%9}, {%0,%1,%2,%3};"        \
                 : "+f"(D[0]), "+f"(D[1]), "+f"(D[2]), "+f"(D[3])               \
                 : "r"(a0), "r"(a1), "r"(a2), "r"(a3), "r"(bb0), "r"(bb1))

__device__ __forceinline__ float sigf(float x)  { return 1.f / (1.f + __expf(-x)); }
__device__ __forceinline__ float tanhf_fast(float x) {
    float e = __expf(2.f * x);
    return (e - 1.f) / (e + 1.f);
}
__device__ __forceinline__ unsigned pack_bf2(__nv_bfloat16 a, __nv_bfloat16 b) {
    return (unsigned)__bfloat16_as_ushort(a) | ((unsigned)__bfloat16_as_ushort(b) << 16);
}
__device__ __forceinline__ float bf_lo(uint32_t v) {
    return __bfloat162float(__ushort_as_bfloat16((unsigned short)(v & 0xFFFF)));
}
__device__ __forceinline__ float bf_hi(uint32_t v) {
    return __bfloat162float(__ushort_as_bfloat16((unsigned short)(v >> 16)));
}

// ---------------------------------------------------------------------------
__global__ void fill_ones_kernel(float4* out, int n4) {
    int i = blockIdx.x * 256 + threadIdx.x;
    if (i < n4) out[i] = make_float4(1.f, 1.f, 1.f, 1.f);
}

__global__ void reset_kernel() {
    for (int d = 0; d < 4; d++) { g_bar_count[d] = 0; g_bar_gen[d] = 0; }
}

// ---------------------------------------------------------------------------
// Split [Wh;Wh2] into bf16 hi/mid, packed by k-pairs: g_Wp*[d][kp][g].
// 4*128*384 = 196608 elems; 768 blocks x 256.
__global__ void wsplit_kernel(const float* __restrict__ Wh,
                              const float* __restrict__ Wh2) {
    int i = blockIdx.x * 256 + threadIdx.x;
    int d  = i / (128 * Gg);
    int kp = (i / Gg) % 128;
    int g  = i % Gg;
    int k0 = 2 * kp, k1 = 2 * kp + 1;
    float w0 = (k0 < 128) ? Wh [((size_t)d * 128 + k0) * Gg + g]
                          : Wh2[((size_t)d * 128 + (k0 - 128)) * Gg + g];
    float w1 = (k1 < 128) ? Wh [((size_t)d * 128 + k1) * Gg + g]
                          : Wh2[((size_t)d * 128 + (k1 - 128)) * Gg + g];
    __nv_bfloat16 h0 = __float2bfloat16(w0);
    __nv_bfloat16 h1 = __float2bfloat16(w1);
    __nv_bfloat16 m0 = __float2bfloat16(w0 - __bfloat162float(h0));
    __nv_bfloat16 m1 = __float2bfloat16(w1 - __bfloat162float(h1));
    g_Wph[i] = pack_bf2(h0, h1);
    g_Wpm[i] = pack_bf2(m0, m1);
}

// ---------------------------------------------------------------------------
// gx precompute (fp32 FFMA — fully parallel, off the critical path)
static constexpr int GX_SMEM = (32 * 68 + 2 * 16 * Gg) * 4;

__global__ void __launch_bounds__(256) gx_kernel(const float* __restrict__ x,
                                                 const float* __restrict__ Wx,
                                                 const float* __restrict__ bias) {
    extern __shared__ float sm[];
    float* Xs  = sm;
    float* Wsb = sm + 32 * 68;

    const int cellpq = blockIdx.x;
    const int d      = blockIdx.y;
    const int p = cellpq / RR, q = cellpq % RR;
    const int ix = (d & 1) ? (62 - p) : p;
    const int jx = (d & 2) ? (62 - q) : q;
    const int t = threadIdx.x;
    const int tx = t & 15, ty = t >> 4;
    const int b0 = ty * 2;
    const float* Wd = Wx + (size_t)d * INC * Gg;

    auto stageW = [&](int kb, int buf) {
        float* W = Wsb + buf * (16 * Gg);
        for (int f = t; f < 16 * 96; f += 256) {
            int kk = f / 96, x16 = f % 96;
            CPA16(smem_u32(W + kk * Gg + x16 * 4),
                  Wd + (size_t)(kb * 16 + kk) * Gg + x16 * 4);
        }
    };
    stageW(0, 0); CPC();
    stageW(1, 1); CPC();

    for (int m = t; m < Bz * INC; m += 256) {
        int b_ = m >> 6, c = m & 63;
        Xs[b_ * 68 + c] = x[((size_t)(b_ * INC + c) << 12) + (ix << 6) + jx];
    }

    float acc[6][4][2];
    const float* bb = bias + d * Gg;
#pragma unroll
    for (int c = 0; c < 6; c++) {
        float4 v = *(const float4*)(bb + c * 64 + tx * 4);
        acc[c][0][0] = v.x; acc[c][0][1] = v.x;
        acc[c][1][0] = v.y; acc[c][1][1] = v.y;
        acc[c][2][0] = v.z; acc[c][2][1] = v.z;
        acc[c][3][0] = v.w; acc[c][3][1] = v.w;
    }

#pragma unroll 1
    for (int kb = 0; kb < 4; kb++) {
        if (kb < 3) { CPW1(); } else { CPW0(); }
        __syncthreads();
        const float* W = Wsb + (kb & 1) * (16 * Gg);
        const float* Arow = Xs + b0 * 68 + kb * 16;
#pragma unroll 8
        for (int kk = 0; kk < 16; kk++) {
            float a0 = Arow[kk];
            float a1 = Arow[68 + kk];
            const float* wr = W + kk * Gg + tx * 4;
#pragma unroll
            for (int c = 0; c < 6; c++) {
                float4 w = *(const float4*)(wr + c * 64);
                acc[c][0][0] += a0 * w.x; acc[c][0][1] += a1 * w.x;
                acc[c][1][0] += a0 * w.y; acc[c][1][1] += a1 * w.y;
                acc[c][2][0] += a0 * w.z; acc[c][2][1] += a1 * w.z;
                acc[c][3][0] += a0 * w.w; acc[c][3][1] += a1 * w.w;
            }
        }
        __syncthreads();
        if (kb < 2) { stageW(kb + 2, kb & 1); CPC(); }
    }

    float* gp = g_gx + ((size_t)(d * CELLS + cellpq) * Bz + b0) * Gg;
#pragma unroll
    for (int c = 0; c < 6; c++) {
#pragma unroll
        for (int b2 = 0; b2 < 2; b2++) {
            *(float4*)(gp + (size_t)b2 * Gg + c * 64 + tx * 4) =
                make_float4(acc[c][0][b2], acc[c][1][b2], acc[c][2][b2], acc[c][3][b2]);
        }
    }
}

// ---------------------------------------------------------------------------
// Persistent bf16x3 wavefront scan. CTA = (d, kq, j), 256 threads / 8 warps.
// Weights (hi+mid, bf16x2 k-pair packed) stationary in SMEM.
// Per task (pair of diagonal cells, M=64): warp (mp, ng) owns cell mp's two
// m16 tiles and n8 group ng of each gate. mma.sync m16n8k16 bf16, 3 split
// passes (ah*bh + am*bh + ah*bm). All-register GRU epilogue.
static constexpr int PAD_W = 104;    // u32 words per W row (96 + 8; 8ci+gi bijective)
static constexpr int PAD_A = 132;    // u32 words per A row (128 + 4; 4gi+ci bijective)
static constexpr int OFF_WPH = 0;                       // [128][104] u32
static constexpr int OFF_WPM = OFF_WPH + 128 * PAD_W;   // [128][104] u32
static constexpr int OFF_AH  = OFF_WPM + 128 * PAD_W;   // [64][132]  u32
static constexpr int OFF_AM  = OFF_AH  + 64 * PAD_A;    // [64][132]  u32
static constexpr int SCAN_SMEM = (OFF_AM + 64 * PAD_A) * 4;   // 174080 B

__device__ __forceinline__ void grid_barrier_d(int d, int gen) {
    __syncthreads();
    if (threadIdx.x == 0) {
        __threadfence();
        if (atomicAdd(&g_bar_count[d], 1) == NCTA_D - 1) {
            g_bar_count[d] = 0;
            __threadfence();
            g_bar_gen[d] = gen;
        } else {
            while (g_bar_gen[d] < gen) { __nanosleep(32); }
            __threadfence();
        }
    }
    __syncthreads();
}

__global__ void __launch_bounds__(256, 1) scan_persist_kernel(float* __restrict__ out) {
    extern __shared__ uint32_t smu[];
    uint32_t* Wph_s = smu + OFF_WPH;
    uint32_t* Wpm_s = smu + OFF_WPM;
    uint32_t* Ah    = smu + OFF_AH;
    uint32_t* Am    = smu + OFF_AM;

    const int cta = blockIdx.x;
    const int d  = cta / 36;
    const int kq = (cta / 9) % 4;
    const int j  = cta % 9;
    const int t  = threadIdx.x;
    const int w = t >> 5, lane = t & 31;
    const int gi = lane >> 2, ci = lane & 3;
    const int mp = w >> 2;      // cell within pair (rows mp*32..+31)
    const int ng = w & 3;       // n8 group within each gate's 32 cols

    // ---- one-time weight staging: col c = gate*32 + koff; kp rows 0..127 ----
    for (int idx = t; idx < 128 * 96; idx += 256) {
        int kp = idx / 96, c = idx % 96;
        int gcol = (c >> 5) * 128 + kq * 32 + (c & 31);
        size_t gsrc = ((size_t)d * 128 + kp) * Gg + gcol;
        Wph_s[kp * PAD_W + c] = g_Wph[gsrc];
        Wpm_s[kp * PAD_W + c] = g_Wpm[gsrc];
    }
    __syncthreads();

    for (int s = 0; s < 2 * RR - 1; s++) {
        const int qlo = (s - (RR - 1) > 0) ? (s - (RR - 1)) : 0;
        const int qhi = (s < RR - 1) ? s : (RR - 1);
        const int npairs = (qhi - qlo + 2) >> 1;

        for (int pi = j; pi < npairs; pi += 9) {
            const int q0 = qlo + 2 * pi;
            const int q1 = q0 + 1;
            const bool c1ok = (q1 <= qhi);
            const int p0 = s - q0;
            const int p1 = s - q1;
            const size_t cell0 = (size_t)d * CELLS + (size_t)p0 * RR + q0;
            const size_t cell1 = (size_t)d * CELLS + (size_t)p1 * RR + q1;

            // ---- stage A: rows 0-31 cell0, 32-63 cell1; k cols [0,128)=h_up,
            //      [128,256)=h_left. __ldcg (L1-bypass: cross-CTA h), bf16
            //      hi/mid split packed by k-pairs.
            {
                const float* hu0 = (p0 > 0) ? g_h + (cell0 - RR) * (Bz * HIDN) : nullptr;
                const float* hl0 = (q0 > 0) ? g_h + (cell0 - 1)  * (Bz * HIDN) : nullptr;
                const float* hu1 = (c1ok && p1 > 0) ? g_h + (cell1 - RR) * (Bz * HIDN) : nullptr;
                const float* hl1 = (c1ok && q1 > 0) ? g_h + (cell1 - 1)  * (Bz * HIDN) : nullptr;
#pragma unroll 4
                for (int f = t; f < 4096; f += 256) {
                    int row = f >> 6;
                    int col = (f & 63) * 4;         // k col, multiple of 4
                    const float* src;
                    if (row < 32)
                        src = (col < 128) ? (hu0 ? hu0 + row * 128 + col : nullptr)
                                          : (hl0 ? hl0 + row * 128 + (col - 128) : nullptr);
                    else
                        src = (col < 128) ? (hu1 ? hu1 + (row - 32) * 128 + col : nullptr)
                                          : (hl1 ? hl1 + (row - 32) * 128 + (col - 128) : nullptr);
                    float4 v = src ? __ldcg((const float4*)src)
                                   : make_float4(0.f, 0.f, 0.f, 0.f);
                    __nv_bfloat16 h0 = __float2bfloat16(v.x), h1 = __float2bfloat16(v.y);
                    __nv_bfloat16 h2 = __float2bfloat16(v.z), h3 = __float2bfloat16(v.w);
                    __nv_bfloat16 m0 = __float2bfloat16(v.x - __bfloat162float(h0));
                    __nv_bfloat16 m1 = __float2bfloat16(v.y - __bfloat162float(h1));
                    __nv_bfloat16 m2 = __float2bfloat16(v.z - __bfloat162float(h2));
                    __nv_bfloat16 m3 = __float2bfloat16(v.w - __bfloat162float(h3));
                    int kp0 = col >> 1;             // even
                    uint2 vh = make_uint2(pack_bf2(h0, h1), pack_bf2(h2, h3));
                    uint2 vm = make_uint2(pack_bf2(m0, m1), pack_bf2(m2, m3));
                    *(uint2*)(Ah + row * PAD_A + kp0) = vh;
                    *(uint2*)(Am + row * PAD_A + kp0) = vm;
                }
                __syncthreads();
            }

            // ---- bf16x3 MMA mainloop over K=256 (16 k16 steps) ----
            float acc[2][3][4];
#pragma unroll
            for (int mt = 0; mt < 2; mt++)
#pragma unroll
                for (int g = 0; g < 3; g++)
#pragma unroll
                    for (int v = 0; v < 4; v++) acc[mt][g][v] = 0.f;

            const int cb0 = ng * 8 + gi;                      // B col within gate
            const uint32_t* AhRow = Ah + (mp * 32 + gi) * PAD_A;
            const uint32_t* AmRow = Am + (mp * 32 + gi) * PAD_A;

#pragma unroll 2
            for (int k16 = 0; k16 < 16; k16++) {
                const int kp0 = k16 * 8;                      // k-pair base
                unsigned bh[3][2], bm[3][2];
#pragma unroll
                for (int g = 0; g < 3; g++) {
                    const int c = g * 32 + cb0;
                    bh[g][0] = Wph_s[(kp0 + ci) * PAD_W + c];
                    bh[g][1] = Wph_s[(kp0 + ci + 4) * PAD_W + c];
                    bm[g][0] = Wpm_s[(kp0 + ci) * PAD_W + c];
                    bm[g][1] = Wpm_s[(kp0 + ci + 4) * PAD_W + c];
                }
#pragma unroll
                for (int mt = 0; mt < 2; mt++) {
                    const uint32_t* Ah0 = AhRow + mt * 16 * PAD_A + kp0;
                    const uint32_t* Am0 = AmRow + mt * 16 * PAD_A + kp0;
                    unsigned ah0 = Ah0[ci],           ah1 = Ah0[8 * PAD_A + ci];
                    unsigned ah2 = Ah0[ci + 4],       ah3 = Ah0[8 * PAD_A + ci + 4];
                    unsigned am0 = Am0[ci],           am1 = Am0[8 * PAD_A + ci];
                    unsigned am2 = Am0[ci + 4],       am3 = Am0[8 * PAD_A + ci + 4];
#pragma unroll
                    for (int g = 0; g < 3; g++) {
                        MMA_BF16(acc[mt][g], ah0, ah1, ah2, ah3, bh[g][0], bh[g][1]); // hi*hi
                        MMA_BF16(acc[mt][g], am0, am1, am2, am3, bh[g][0], bh[g][1]); // mid*hi
                        MMA_BF16(acc[mt][g], ah0, ah1, ah2, ah3, bm[g][0], bm[g][1]); // hi*mid
                    }
                }
            }

            // ---- GRU epilogue: warp's cell = mp ----
            if (!(mp == 1 && !c1ok)) {
                const size_t cell = mp ? cell1 : cell0;
                const int p = mp ? p1 : p0;
                const int q = mp ? q1 : q0;
                const int oi = (d & 1) ? (63 - p) : p;
                const int oj = (d & 2) ? (63 - q) : q;
                float* hdst = g_h + cell * (Bz * HIDN);
                const int kbase = kq * 32 + ng * 8 + 2 * ci;   // kg for c=0
                const int kp = kbase >> 1;                      // pair index (<64)
#pragma unroll
                for (int mt = 0; mt < 2; mt++) {
#pragma unroll
                    for (int half = 0; half < 2; half++) {
                        const int b = mt * 16 + half * 8 + gi;  // batch
                        const int row = mp * 32 + b;            // A row
                        const float* gxc = g_gx + (cell * Bz + b) * Gg;
                        float2 gr = __ldcg((const float2*)(gxc + kbase));
                        float2 gz = __ldcg((const float2*)(gxc + 128 + kbase));
                        float2 gn = __ldcg((const float2*)(gxc + 256 + kbase));
                        uint32_t huH = Ah[row * PAD_A + kp];
                        uint32_t huM = Am[row * PAD_A + kp];
                        uint32_t hlH = Ah[row * PAD_A + 64 + kp];
                        uint32_t hlM = Am[row * PAD_A + 64 + kp];
                        float hu0 = bf_lo(huH) + bf_lo(huM);
                        float hu1 = bf_hi(huH) + bf_hi(huM);
                        float hl0 = bf_lo(hlH) + bf_lo(hlM);
                        float hl1 = bf_hi(hlH) + bf_hi(hlM);
                        float r0 = sigf(acc[mt][0][half * 2 + 0] + gr.x);
                        float r1 = sigf(acc[mt][0][half * 2 + 1] + gr.y);
                        float z0 = sigf(acc[mt][1][half * 2 + 0] + gz.x);
                        float z1 = sigf(acc[mt][1][half * 2 + 1] + gz.y);
                        float n0 = tanhf_fast(gn.x + r0 * acc[mt][2][half * 2 + 0]);
                        float n1 = tanhf_fast(gn.y + r1 * acc[mt][2][half * 2 + 1]);
                        float h0 = (1.f - z0) * n0 + z0 * 0.5f * (hu0 + hl0);
                        float h1 = (1.f - z1) * n1 + z1 * 0.5f * (hu1 + hl1);
                        hdst[b * 128 + kbase]     = h0;
                        hdst[b * 128 + kbase + 1] = h1;
                        size_t ob = ((size_t)(b * 128 + kbase) * 4 + d) * 4096
                                    + (size_t)oi * 64 + oj;
                        out[ob]          = h0;
                        out[ob + 16384]  = h1;   // (+1 k) * 4 * 4096
                    }
                }
            }
            __syncthreads();   // protect A before next pair overwrites it
        }

        grid_barrier_d(d, s + 1);
    }
}

// ---------------------------------------------------------------------------
extern "C" void kernel_launch(void* const* d_in, const int* in_sizes, int n_in,
                              void* d_out, int out_size) {
    const float* x    = (const float*)d_in[0];
    const float* Wx   = (const float*)d_in[1];
    const float* Wh   = (const float*)d_in[2];
    const float* Wh2  = (const float*)d_in[3];
    const float* bias = (const float*)d_in[4];
    float* out = (float*)d_out;

    cudaFuncSetAttribute(gx_kernel, cudaFuncAttributeMaxDynamicSharedMemorySize, GX_SMEM);
    cudaFuncSetAttribute(scan_persist_kernel,
                         cudaFuncAttributeMaxDynamicSharedMemorySize, SCAN_SMEM);

    // 1) independent prep
    int n4 = out_size / 4;
    fill_ones_kernel<<<(n4 + 255) / 256, 256>>>((float4*)d_out, n4);
    wsplit_kernel<<<768, 256>>>(Wh, Wh2);
    reset_kernel<<<1, 1>>>();

    // 2) gx precompute
    {
        dim3 grid(CELLS, 4);
        gx_kernel<<<grid, 256, GX_SMEM>>>(x, Wx, bias);
    }

    // 3) persistent bf16x3 wavefront scan (single launch; weights SMEM-resident)
    scan_persist_kernel<<<NCTAS, 256, SCAN_SMEM>>>(out);
}

// round 12
// speedup vs baseline: 2.1526x; 1.4760x over previous
#include <cuda_runtime.h>
#include <cuda_bf16.h>
#include <cstdint>
#include <math.h>

// Problem constants
static constexpr int Bz   = 32;
static constexpr int INC  = 64;
static constexpr int HIDN = 128;
static constexpr int Gg   = 384;
static constexpr int RR   = 63;
static constexpr int CELLS = RR * RR; // 3969
static constexpr int NCTA_D = 36;     // CTAs per direction (4 kq x 9)
static constexpr int NCTAS  = 144;

// Scratch (allocation-free: __device__ globals)
__device__ float g_gx [(size_t)4 * CELLS * Bz * Gg];    // gx = x@Wx + b   [d][p][q][b][g]
__device__ uint32_t g_hph[(size_t)4 * CELLS * Bz * 64]; // h hi  (bf16x2 k-pair packed) [d][p][q][b][kp]
__device__ uint32_t g_hpm[(size_t)4 * CELLS * Bz * 64]; // h mid residual               [d][p][q][b][kp]
__device__ uint32_t g_Wph[(size_t)4 * 128 * Gg];        // bf16x2 hi of [Wh;Wh2], k-pair packed [d][kp][g]
__device__ uint32_t g_Wpm[(size_t)4 * 128 * Gg];        // bf16x2 mid residual                 [d][kp][g]
__device__ int          g_bar_count[4];
__device__ volatile int g_bar_gen[4];

// ---------------------------------------------------------------------------
__device__ __forceinline__ unsigned smem_u32(const void* p) {
    return (unsigned)__cvta_generic_to_shared(p);
}
#define CPA16(dst, src) asm volatile("cp.async.cg.shared.global [%0], [%1], 16;" :: "r"(dst), "l"(src))
#define CPC()  asm volatile("cp.async.commit_group;")
#define CPW0() asm volatile("cp.async.wait_group 0;")
#define CPW1() asm volatile("cp.async.wait_group 1;")

#define MMA_BF16(D, a0, a1, a2, a3, bb0, bb1)                                   \
    asm volatile("mma.sync.aligned.m16n8k16.row.col.f32.bf16.bf16.f32 "         \
                 "{%0,%1,%2,%3}, {%4,%5,%6,%7}, {%8,%9}, {%0,%1,%2,%3};"        \
                 : "+f"(D[0]), "+f"(D[1]), "+f"(D[2]), "+f"(D[3])               \
                 : "r"(a0), "r"(a1), "r"(a2), "r"(a3), "r"(bb0), "r"(bb1))

__device__ __forceinline__ float sigf(float x)  { return 1.f / (1.f + __expf(-x)); }
__device__ __forceinline__ float tanhf_fast(float x) {
    float e = __expf(2.f * x);
    return (e - 1.f) / (e + 1.f);
}
__device__ __forceinline__ unsigned pack_bf2(__nv_bfloat16 a, __nv_bfloat16 b) {
    return (unsigned)__bfloat16_as_ushort(a) | ((unsigned)__bfloat16_as_ushort(b) << 16);
}
__device__ __forceinline__ float bf_lo(uint32_t v) {
    return __bfloat162float(__ushort_as_bfloat16((unsigned short)(v & 0xFFFF)));
}
__device__ __forceinline__ float bf_hi(uint32_t v) {
    return __bfloat162float(__ushort_as_bfloat16((unsigned short)(v >> 16)));
}
__device__ __forceinline__ uint32_t split_pack_hi(float a, float b,
                                                  __nv_bfloat16& ha, __nv_bfloat16& hb) {
    ha = __float2bfloat16(a);
    hb = __float2bfloat16(b);
    return pack_bf2(ha, hb);
}

// ---------------------------------------------------------------------------
__global__ void fill_ones_kernel(float4* out, int n4) {
    int i = blockIdx.x * 256 + threadIdx.x;
    if (i < n4) out[i] = make_float4(1.f, 1.f, 1.f, 1.f);
}

__global__ void reset_kernel() {
    for (int d = 0; d < 4; d++) { g_bar_count[d] = 0; g_bar_gen[d] = 0; }
}

// ---------------------------------------------------------------------------
// Split [Wh;Wh2] into bf16 hi/mid, packed by k-pairs: g_Wp*[d][kp][g].
__global__ void wsplit_kernel(const float* __restrict__ Wh,
                              const float* __restrict__ Wh2) {
    int i = blockIdx.x * 256 + threadIdx.x;
    int d  = i / (128 * Gg);
    int kp = (i / Gg) % 128;
    int g  = i % Gg;
    int k0 = 2 * kp, k1 = 2 * kp + 1;
    float w0 = (k0 < 128) ? Wh [((size_t)d * 128 + k0) * Gg + g]
                          : Wh2[((size_t)d * 128 + (k0 - 128)) * Gg + g];
    float w1 = (k1 < 128) ? Wh [((size_t)d * 128 + k1) * Gg + g]
                          : Wh2[((size_t)d * 128 + (k1 - 128)) * Gg + g];
    __nv_bfloat16 h0 = __float2bfloat16(w0);
    __nv_bfloat16 h1 = __float2bfloat16(w1);
    __nv_bfloat16 m0 = __float2bfloat16(w0 - __bfloat162float(h0));
    __nv_bfloat16 m1 = __float2bfloat16(w1 - __bfloat162float(h1));
    g_Wph[i] = pack_bf2(h0, h1);
    g_Wpm[i] = pack_bf2(m0, m1);
}

// ---------------------------------------------------------------------------
// gx precompute (fp32 FFMA — fully parallel, off the critical path)
static constexpr int GX_SMEM = (32 * 68 + 2 * 16 * Gg) * 4;

__global__ void __launch_bounds__(256) gx_kernel(const float* __restrict__ x,
                                                 const float* __restrict__ Wx,
                                                 const float* __restrict__ bias) {
    extern __shared__ float sm[];
    float* Xs  = sm;
    float* Wsb = sm + 32 * 68;

    const int cellpq = blockIdx.x;
    const int d      = blockIdx.y;
    const int p = cellpq / RR, q = cellpq % RR;
    const int ix = (d & 1) ? (62 - p) : p;
    const int jx = (d & 2) ? (62 - q) : q;
    const int t = threadIdx.x;
    const int tx = t & 15, ty = t >> 4;
    const int b0 = ty * 2;
    const float* Wd = Wx + (size_t)d * INC * Gg;

    auto stageW = [&](int kb, int buf) {
        float* W = Wsb + buf * (16 * Gg);
        for (int f = t; f < 16 * 96; f += 256) {
            int kk = f / 96, x16 = f % 96;
            CPA16(smem_u32(W + kk * Gg + x16 * 4),
                  Wd + (size_t)(kb * 16 + kk) * Gg + x16 * 4);
        }
    };
    stageW(0, 0); CPC();
    stageW(1, 1); CPC();

    for (int m = t; m < Bz * INC; m += 256) {
        int b_ = m >> 6, c = m & 63;
        Xs[b_ * 68 + c] = x[((size_t)(b_ * INC + c) << 12) + (ix << 6) + jx];
    }

    float acc[6][4][2];
    const float* bb = bias + d * Gg;
#pragma unroll
    for (int c = 0; c < 6; c++) {
        float4 v = *(const float4*)(bb + c * 64 + tx * 4);
        acc[c][0][0] = v.x; acc[c][0][1] = v.x;
        acc[c][1][0] = v.y; acc[c][1][1] = v.y;
        acc[c][2][0] = v.z; acc[c][2][1] = v.z;
        acc[c][3][0] = v.w; acc[c][3][1] = v.w;
    }

#pragma unroll 1
    for (int kb = 0; kb < 4; kb++) {
        if (kb < 3) { CPW1(); } else { CPW0(); }
        __syncthreads();
        const float* W = Wsb + (kb & 1) * (16 * Gg);
        const float* Arow = Xs + b0 * 68 + kb * 16;
#pragma unroll 8
        for (int kk = 0; kk < 16; kk++) {
            float a0 = Arow[kk];
            float a1 = Arow[68 + kk];
            const float* wr = W + kk * Gg + tx * 4;
#pragma unroll
            for (int c = 0; c < 6; c++) {
                float4 w = *(const float4*)(wr + c * 64);
                acc[c][0][0] += a0 * w.x; acc[c][0][1] += a1 * w.x;
                acc[c][1][0] += a0 * w.y; acc[c][1][1] += a1 * w.y;
                acc[c][2][0] += a0 * w.z; acc[c][2][1] += a1 * w.z;
                acc[c][3][0] += a0 * w.w; acc[c][3][1] += a1 * w.w;
            }
        }
        __syncthreads();
        if (kb < 2) { stageW(kb + 2, kb & 1); CPC(); }
    }

    float* gp = g_gx + ((size_t)(d * CELLS + cellpq) * Bz + b0) * Gg;
#pragma unroll
    for (int c = 0; c < 6; c++) {
#pragma unroll
        for (int b2 = 0; b2 < 2; b2++) {
            *(float4*)(gp + (size_t)b2 * Gg + c * 64 + tx * 4) =
                make_float4(acc[c][0][b2], acc[c][1][b2], acc[c][2][b2], acc[c][3][b2]);
        }
    }
}

// ---------------------------------------------------------------------------
// Persistent bf16x3 wavefront scan. CTA = (d, kq, j), 256 threads / 8 warps.
// h stored pre-split (g_hph/g_hpm) -> A staging is a pure cp.async copy.
// No out stores in the scan; a post-scan transpose kernel scatters h -> out.
static constexpr int PAD_W = 104;    // u32 words per W row (96 + 8; 8ci+gi bijective)
static constexpr int PAD_A = 132;    // u32 words per A row (128 + 4; 4gi+ci bijective)
static constexpr int OFF_WPH = 0;                       // [128][104] u32
static constexpr int OFF_WPM = OFF_WPH + 128 * PAD_W;   // [128][104] u32
static constexpr int OFF_AH  = OFF_WPM + 128 * PAD_W;   // [64][132]  u32
static constexpr int OFF_AM  = OFF_AH  + 64 * PAD_A;    // [64][132]  u32
static constexpr int SCAN_SMEM = (OFF_AM + 64 * PAD_A) * 4;   // 174080 B

__device__ __forceinline__ void grid_barrier_d(int d, int gen) {
    __syncthreads();
    if (threadIdx.x == 0) {
        __threadfence();
        if (atomicAdd(&g_bar_count[d], 1) == NCTA_D - 1) {
            g_bar_count[d] = 0;
            __threadfence();
            g_bar_gen[d] = gen;
        } else {
            while (g_bar_gen[d] < gen) { __nanosleep(32); }
            __threadfence();
        }
    }
    __syncthreads();
}

__global__ void __launch_bounds__(256, 1) scan_persist_kernel() {
    extern __shared__ uint32_t smu[];
    uint32_t* Wph_s = smu + OFF_WPH;
    uint32_t* Wpm_s = smu + OFF_WPM;
    uint32_t* Ah    = smu + OFF_AH;
    uint32_t* Am    = smu + OFF_AM;

    const int cta = blockIdx.x;
    const int d  = cta / 36;
    const int kq = (cta / 9) % 4;
    const int j  = cta % 9;
    const int t  = threadIdx.x;
    const int w = t >> 5, lane = t & 31;
    const int gi = lane >> 2, ci = lane & 3;
    const int mp = w >> 2;      // cell within pair (rows mp*32..+31)
    const int ng = w & 3;       // n8 group within each gate's 32 cols

    // ---- one-time weight staging: col c = gate*32 + koff; kp rows 0..127 ----
    for (int idx = t; idx < 128 * 96; idx += 256) {
        int kp = idx / 96, c = idx % 96;
        int gcol = (c >> 5) * 128 + kq * 32 + (c & 31);
        size_t gsrc = ((size_t)d * 128 + kp) * Gg + gcol;
        Wph_s[kp * PAD_W + c] = g_Wph[gsrc];
        Wpm_s[kp * PAD_W + c] = g_Wpm[gsrc];
    }
    __syncthreads();

    for (int s = 0; s < 2 * RR - 1; s++) {
        const int qlo = (s - (RR - 1) > 0) ? (s - (RR - 1)) : 0;
        const int qhi = (s < RR - 1) ? s : (RR - 1);
        const int npairs = (qhi - qlo + 2) >> 1;

        for (int pi = j; pi < npairs; pi += 9) {
            const int q0 = qlo + 2 * pi;
            const int q1 = q0 + 1;
            const bool c1ok = (q1 <= qhi);
            const int p0 = s - q0;
            const int p1 = s - q1;
            const size_t cell0 = (size_t)d * CELLS + (size_t)p0 * RR + q0;
            const size_t cell1 = (size_t)d * CELLS + (size_t)p1 * RR + q1;

            // ---- stage A (pure cp.async copy of pre-split h):
            //      rows 0-31 cell0, 32-63 cell1; kp cols [0,64)=h_up, [64,128)=h_left
            {
#pragma unroll
                for (int f0 = 0; f0 < 2048; f0 += 256) {
                    const int f = f0 + t;
                    const int row = f >> 5;             // 0..63
                    const int c4  = (f & 31) * 4;       // u32 col, 16B aligned
                    const int cIdx = row >> 5;
                    const int b = row & 31;
                    const bool isUp = (c4 < 64);
                    const int kloc = isUp ? c4 : (c4 - 64);
                    bool valid;
                    size_t srcCell;
                    if (cIdx == 0) {
                        valid = isUp ? (p0 > 0) : (q0 > 0);
                        srcCell = isUp ? (cell0 - RR) : (cell0 - 1);
                    } else {
                        valid = c1ok && (isUp ? (p1 > 0) : (q1 > 0));
                        srcCell = isUp ? (cell1 - RR) : (cell1 - 1);
                    }
                    uint32_t* dh = Ah + row * PAD_A + c4;
                    uint32_t* dm = Am + row * PAD_A + c4;
                    if (valid) {
                        size_t off = (srcCell * Bz + b) * 64 + kloc;
                        CPA16(smem_u32(dh), g_hph + off);
                        CPA16(smem_u32(dm), g_hpm + off);
                    } else {
                        *(uint4*)dh = make_uint4(0u, 0u, 0u, 0u);
                        *(uint4*)dm = make_uint4(0u, 0u, 0u, 0u);
                    }
                }
                CPC(); CPW0();
                __syncthreads();
            }

            // ---- bf16x3 MMA mainloop over K=256 (16 k16 steps) ----
            float acc[2][3][4];
#pragma unroll
            for (int mt = 0; mt < 2; mt++)
#pragma unroll
                for (int g = 0; g < 3; g++)
#pragma unroll
                    for (int v = 0; v < 4; v++) acc[mt][g][v] = 0.f;

            const int cb0 = ng * 8 + gi;                      // B col within gate
            const uint32_t* AhRow = Ah + (mp * 32 + gi) * PAD_A;
            const uint32_t* AmRow = Am + (mp * 32 + gi) * PAD_A;

#pragma unroll 2
            for (int k16 = 0; k16 < 16; k16++) {
                const int kp0 = k16 * 8;                      // k-pair base
                unsigned bh[3][2], bm[3][2];
#pragma unroll
                for (int g = 0; g < 3; g++) {
                    const int c = g * 32 + cb0;
                    bh[g][0] = Wph_s[(kp0 + ci) * PAD_W + c];
                    bh[g][1] = Wph_s[(kp0 + ci + 4) * PAD_W + c];
                    bm[g][0] = Wpm_s[(kp0 + ci) * PAD_W + c];
                    bm[g][1] = Wpm_s[(kp0 + ci + 4) * PAD_W + c];
                }
#pragma unroll
                for (int mt = 0; mt < 2; mt++) {
                    const uint32_t* Ah0 = AhRow + mt * 16 * PAD_A + kp0;
                    const uint32_t* Am0 = AmRow + mt * 16 * PAD_A + kp0;
                    unsigned ah0 = Ah0[ci],           ah1 = Ah0[8 * PAD_A + ci];
                    unsigned ah2 = Ah0[ci + 4],       ah3 = Ah0[8 * PAD_A + ci + 4];
                    unsigned am0 = Am0[ci],           am1 = Am0[8 * PAD_A + ci];
                    unsigned am2 = Am0[ci + 4],       am3 = Am0[8 * PAD_A + ci + 4];
#pragma unroll
                    for (int g = 0; g < 3; g++) {
                        MMA_BF16(acc[mt][g], ah0, ah1, ah2, ah3, bh[g][0], bh[g][1]); // hi*hi
                        MMA_BF16(acc[mt][g], am0, am1, am2, am3, bh[g][0], bh[g][1]); // mid*hi
                        MMA_BF16(acc[mt][g], ah0, ah1, ah2, ah3, bm[g][0], bm[g][1]); // hi*mid
                    }
                }
            }

            // ---- GRU epilogue: warp's cell = mp; store pre-split h only ----
            if (!(mp == 1 && !c1ok)) {
                const size_t cell = mp ? cell1 : cell0;
                const int kbase = kq * 32 + ng * 8 + 2 * ci;   // k for c=0
                const int kp = kbase >> 1;                      // pair index (<64)
#pragma unroll
                for (int mt = 0; mt < 2; mt++) {
#pragma unroll
                    for (int half = 0; half < 2; half++) {
                        const int b = mt * 16 + half * 8 + gi;  // batch
                        const int row = mp * 32 + b;            // A row
                        const float* gxc = g_gx + (cell * Bz + b) * Gg;
                        float2 gr = __ldcg((const float2*)(gxc + kbase));
                        float2 gz = __ldcg((const float2*)(gxc + 128 + kbase));
                        float2 gn = __ldcg((const float2*)(gxc + 256 + kbase));
                        uint32_t huH = Ah[row * PAD_A + kp];
                        uint32_t huM = Am[row * PAD_A + kp];
                        uint32_t hlH = Ah[row * PAD_A + 64 + kp];
                        uint32_t hlM = Am[row * PAD_A + 64 + kp];
                        float hu0 = bf_lo(huH) + bf_lo(huM);
                        float hu1 = bf_hi(huH) + bf_hi(huM);
                        float hl0 = bf_lo(hlH) + bf_lo(hlM);
                        float hl1 = bf_hi(hlH) + bf_hi(hlM);
                        float r0 = sigf(acc[mt][0][half * 2 + 0] + gr.x);
                        float r1 = sigf(acc[mt][0][half * 2 + 1] + gr.y);
                        float z0 = sigf(acc[mt][1][half * 2 + 0] + gz.x);
                        float z1 = sigf(acc[mt][1][half * 2 + 1] + gz.y);
                        float n0 = tanhf_fast(gn.x + r0 * acc[mt][2][half * 2 + 0]);
                        float n1 = tanhf_fast(gn.y + r1 * acc[mt][2][half * 2 + 1]);
                        float h0 = (1.f - z0) * n0 + z0 * 0.5f * (hu0 + hl0);
                        float h1 = (1.f - z1) * n1 + z1 * 0.5f * (hu1 + hl1);
                        __nv_bfloat16 H0, H1;
                        uint32_t vh = split_pack_hi(h0, h1, H0, H1);
                        uint32_t vm = pack_bf2(
                            __float2bfloat16(h0 - __bfloat162float(H0)),
                            __float2bfloat16(h1 - __bfloat162float(H1)));
                        size_t off = (cell * Bz + b) * 64 + kp;
                        g_hph[off] = vh;
                        g_hpm[off] = vm;
                    }
                }
            }
            __syncthreads();   // protect A before next pair overwrites it
        }

        grid_barrier_d(d, s + 1);
    }
}

// ---------------------------------------------------------------------------
// Post-scan scatter: h (= hi + mid) -> out[b][k][d][i][j], smem-tiled so both
// sides are 128B-coalesced. Block = (d, b, p, q-tile of 32).
__global__ void __launch_bounds__(256) scatter_kernel(float* __restrict__ out) {
    __shared__ float sm[32][129];
    const int bx = blockIdx.x;          // p*2 + qt
    const int b  = blockIdx.y;
    const int d  = blockIdx.z;
    const int p  = bx >> 1;
    const int qt = bx & 1;
    const int qb = qt * 32;
    const int nq = qt ? 31 : 32;        // q in [qb, qb+nq)
    const int t  = threadIdx.x;

    // read: per q-row, 64 u32 (hph) + 64 (hpm), contiguous 256B
    for (int idx = t; idx < nq * 64; idx += 256) {
        const int qi = idx >> 6;
        const int kp = idx & 63;
        const size_t cell = (size_t)d * CELLS + (size_t)p * RR + (qb + qi);
        const size_t off = (cell * Bz + b) * 64 + kp;
        uint32_t vh = g_hph[off];
        uint32_t vm = g_hpm[off];
        sm[qi][2 * kp]     = bf_lo(vh) + bf_lo(vm);
        sm[qi][2 * kp + 1] = bf_hi(vh) + bf_hi(vm);
    }
    __syncthreads();

    const int oi = (d & 1) ? (63 - p) : p;
    // write: lanes sweep q -> consecutive oj (forward or reversed), 128B stores
    for (int idx = t; idx < 32 * 128; idx += 256) {
        const int k  = idx >> 5;
        const int qi = idx & 31;
        if (qi < nq) {
            const int q  = qb + qi;
            const int oj = (d & 2) ? (63 - q) : q;
            out[((size_t)(b * 128 + k) * 4 + d) * 4096 + (size_t)oi * 64 + oj]
                = sm[qi][k];
        }
    }
}

// ---------------------------------------------------------------------------
extern "C" void kernel_launch(void* const* d_in, const int* in_sizes, int n_in,
                              void* d_out, int out_size) {
    const float* x    = (const float*)d_in[0];
    const float* Wx   = (const float*)d_in[1];
    const float* Wh   = (const float*)d_in[2];
    const float* Wh2  = (const float*)d_in[3];
    const float* bias = (const float*)d_in[4];
    float* out = (float*)d_out;

    cudaFuncSetAttribute(gx_kernel, cudaFuncAttributeMaxDynamicSharedMemorySize, GX_SMEM);
    cudaFuncSetAttribute(scan_persist_kernel,
                         cudaFuncAttributeMaxDynamicSharedMemorySize, SCAN_SMEM);

    // 1) independent prep
    int n4 = out_size / 4;
    fill_ones_kernel<<<(n4 + 255) / 256, 256>>>((float4*)d_out, n4);
    wsplit_kernel<<<768, 256>>>(Wh, Wh2);
    reset_kernel<<<1, 1>>>();

    // 2) gx precompute
    {
        dim3 grid(CELLS, 4);
        gx_kernel<<<grid, 256, GX_SMEM>>>(x, Wx, bias);
    }

    // 3) persistent bf16x3 wavefront scan (single launch; weights SMEM-resident)
    scan_persist_kernel<<<NCTAS, 256, SCAN_SMEM>>>();

    // 4) coalesced transpose of h into the output layout
    {
        dim3 grid(126, 32, 4);
        scatter_kernel<<<grid, 256>>>(out);
    }
}

// round 13
// speedup vs baseline: 2.6197x; 1.2170x over previous
#include <cuda_runtime.h>
#include <cuda_bf16.h>
#include <cstdint>
#include <math.h>

// Problem constants
static constexpr int Bz   = 32;
static constexpr int INC  = 64;
static constexpr int HIDN = 128;
static constexpr int Gg   = 384;
static constexpr int RR   = 63;
static constexpr int CELLS = RR * RR; // 3969
static constexpr int NCTA_D = 36;     // CTAs per direction (4 kq x 9)
static constexpr int NCTAS  = 144;

// Scratch (allocation-free: __device__ globals)
__device__ float g_gx [(size_t)4 * CELLS * Bz * Gg];    // gx = x@Wx + b   [d][p][q][b][g]
__device__ uint32_t g_hph[(size_t)4 * CELLS * Bz * 64]; // h hi  (bf16x2 k-pair packed) [d][p][q][b][kp]
__device__ uint32_t g_hpm[(size_t)4 * CELLS * Bz * 64]; // h mid residual               [d][p][q][b][kp]
__device__ uint32_t g_Wph[(size_t)4 * 128 * Gg];        // bf16x2 hi of [Wh;Wh2], k-pair packed [d][kp][g]
__device__ uint32_t g_Wpm[(size_t)4 * 128 * Gg];        // bf16x2 mid residual                 [d][kp][g]
__device__ uint32_t g_Wxh[(size_t)4 * 32 * Gg];         // bf16x2 hi of Wx, c-pair packed [d][kp][g]
__device__ uint32_t g_Wxm[(size_t)4 * 32 * Gg];         // bf16x2 mid residual            [d][kp][g]
__device__ uint32_t g_xph[(size_t)4096 * Bz * 32];      // x hi  (bf16x2 c-pair) [i*64+j][b][kp]
__device__ uint32_t g_xpm[(size_t)4096 * Bz * 32];      // x mid residual        [i*64+j][b][kp]
__device__ int          g_bar_count[4];
__device__ volatile int g_bar_gen[4];

// ---------------------------------------------------------------------------
__device__ __forceinline__ unsigned smem_u32(const void* p) {
    return (unsigned)__cvta_generic_to_shared(p);
}
#define CPA16(dst, src) asm volatile("cp.async.cg.shared.global [%0], [%1], 16;" :: "r"(dst), "l"(src))
#define CPC()  asm volatile("cp.async.commit_group;")
#define CPW0() asm volatile("cp.async.wait_group 0;")

#define MMA_BF16(D, a0, a1, a2, a3, bb0, bb1)                                   \
    asm volatile("mma.sync.aligned.m16n8k16.row.col.f32.bf16.bf16.f32 "         \
                 "{%0,%1,%2,%3}, {%4,%5,%6,%7}, {%8,%9}, {%0,%1,%2,%3};"        \
                 : "+f"(D[0]), "+f"(D[1]), "+f"(D[2]), "+f"(D[3])               \
                 : "r"(a0), "r"(a1), "r"(a2), "r"(a3), "r"(bb0), "r"(bb1))

__device__ __forceinline__ float sigf(float x)  { return 1.f / (1.f + __expf(-x)); }
__device__ __forceinline__ float tanhf_fast(float x) {
    float e = __expf(2.f * x);
    return (e - 1.f) / (e + 1.f);
}
__device__ __forceinline__ unsigned pack_bf2(__nv_bfloat16 a, __nv_bfloat16 b) {
    return (unsigned)__bfloat16_as_ushort(a) | ((unsigned)__bfloat16_as_ushort(b) << 16);
}
__device__ __forceinline__ float bf_lo(uint32_t v) {
    return __bfloat162float(__ushort_as_bfloat16((unsigned short)(v & 0xFFFF)));
}
__device__ __forceinline__ float bf_hi(uint32_t v) {
    return __bfloat162float(__ushort_as_bfloat16((unsigned short)(v >> 16)));
}
__device__ __forceinline__ void split2(float a, float b, uint32_t& vh, uint32_t& vm) {
    __nv_bfloat16 ha = __float2bfloat16(a);
    __nv_bfloat16 hb = __float2bfloat16(b);
    vh = pack_bf2(ha, hb);
    vm = pack_bf2(__float2bfloat16(a - __bfloat162float(ha)),
                  __float2bfloat16(b - __bfloat162float(hb)));
}

// ---------------------------------------------------------------------------
__global__ void fill_ones_kernel(float4* out, int n4) {
    int i = blockIdx.x * 256 + threadIdx.x;
    if (i < n4) out[i] = make_float4(1.f, 1.f, 1.f, 1.f);
}

__global__ void reset_kernel() {
    for (int d = 0; d < 4; d++) { g_bar_count[d] = 0; g_bar_gen[d] = 0; }
}

// ---------------------------------------------------------------------------
// Split [Wh;Wh2] into bf16 hi/mid, packed by k-pairs: g_Wp*[d][kp][g].
__global__ void wsplit_kernel(const float* __restrict__ Wh,
                              const float* __restrict__ Wh2) {
    int i = blockIdx.x * 256 + threadIdx.x;
    int d  = i / (128 * Gg);
    int kp = (i / Gg) % 128;
    int g  = i % Gg;
    int k0 = 2 * kp, k1 = 2 * kp + 1;
    float w0 = (k0 < 128) ? Wh [((size_t)d * 128 + k0) * Gg + g]
                          : Wh2[((size_t)d * 128 + (k0 - 128)) * Gg + g];
    float w1 = (k1 < 128) ? Wh [((size_t)d * 128 + k1) * Gg + g]
                          : Wh2[((size_t)d * 128 + (k1 - 128)) * Gg + g];
    split2(w0, w1, g_Wph[i], g_Wpm[i]);
}

// Split Wx into bf16 hi/mid, packed by c-pairs: g_Wx*[d][kp][g].
__global__ void wxsplit_kernel(const float* __restrict__ Wx) {
    int i = blockIdx.x * 256 + threadIdx.x;   // 4*32*384 = 49152
    int d  = i / (32 * Gg);
    int kp = (i / Gg) % 32;
    int g  = i % Gg;
    float w0 = Wx[((size_t)d * INC + 2 * kp)     * Gg + g];
    float w1 = Wx[((size_t)d * INC + 2 * kp + 1) * Gg + g];
    split2(w0, w1, g_Wxh[i], g_Wxm[i]);
}

// Transpose+split x: x[b][c][i][j] -> g_xp*[i*64+j][b][kp(c/2)] (bf16x2).
// Block per (i*64+j); threads sweep (b,kp) -> contiguous 4KB writes.
__global__ void __launch_bounds__(256) xsplit_kernel(const float* __restrict__ x) {
    const int ij = blockIdx.x;            // 0..4095
    const int t = threadIdx.x;
#pragma unroll
    for (int f0 = 0; f0 < 1024; f0 += 256) {
        int f = f0 + t;
        int b = f >> 5, kp = f & 31;
        float v0 = x[(((size_t)b * INC + 2 * kp)     << 12) + ij];
        float v1 = x[(((size_t)b * INC + 2 * kp + 1) << 12) + ij];
        uint32_t vh, vm;
        split2(v0, v1, vh, vm);
        size_t off = (size_t)ij * (Bz * 32) + f;
        g_xph[off] = vh;
        g_xpm[off] = vm;
    }
}

// ---------------------------------------------------------------------------
// gx via bf16x3 mma: CTA = (d, p, q-pair). A = [64 rows = 2 cells x 32 b][64 c]
// copied pre-split from g_xp*; W = Wx tiles in SMEM. D[64][384] + bias -> g_gx.
static constexpr int GXM_PW = 392;   // u32 per W row (384 + 8)
static constexpr int GXM_PA = 36;    // u32 per A row (32 + 4)
static constexpr int GXM_OFF_WH = 0;                         // [32][392]
static constexpr int GXM_OFF_WM = GXM_OFF_WH + 32 * GXM_PW;  // [32][392]
static constexpr int GXM_OFF_AH = GXM_OFF_WM + 32 * GXM_PW;  // [64][36]
static constexpr int GXM_OFF_AM = GXM_OFF_AH + 64 * GXM_PA;  // [64][36]
static constexpr int GXM_OFF_BIAS = GXM_OFF_AM + 64 * GXM_PA; // [384] f32
static constexpr int GXM_SMEM = (GXM_OFF_BIAS + Gg) * 4;      // 121856 B

__global__ void __launch_bounds__(256) gx_mma_kernel(const float* __restrict__ bias) {
    extern __shared__ uint32_t smu[];
    uint32_t* Wh_s = smu + GXM_OFF_WH;
    uint32_t* Wm_s = smu + GXM_OFF_WM;
    uint32_t* Ah   = smu + GXM_OFF_AH;
    uint32_t* Am   = smu + GXM_OFF_AM;
    float*    bs   = (float*)(smu + GXM_OFF_BIAS);

    const int pair = blockIdx.x;          // 0..31
    const int p    = blockIdx.y;          // 0..62
    const int d    = blockIdx.z;
    const int q0 = 2 * pair;
    const int q1 = q0 + 1;
    const bool c1ok = (q1 < RR);
    const int t = threadIdx.x;
    const int w = t >> 5, lane = t & 31;
    const int gi = lane >> 2, ci = lane & 3;
    const int mp = w >> 2;                // cell within pair
    const int ng = w & 3;                 // 96-col n-chunk

    // ---- stage A (pure cp.async from pre-split x) + W + bias ----
    {
        const int ix = (d & 1) ? (62 - p) : p;
        const int jx0 = (d & 2) ? (62 - q0) : q0;
        const int jx1 = (d & 2) ? (62 - q1) : q1;
        const uint32_t* srcs_h[2] = {
            g_xph + (size_t)(ix * 64 + jx0) * 1024,
            g_xph + (size_t)(ix * 64 + jx1) * 1024 };
        const uint32_t* srcs_m[2] = {
            g_xpm + (size_t)(ix * 64 + jx0) * 1024,
            g_xpm + (size_t)(ix * 64 + jx1) * 1024 };
#pragma unroll
        for (int f0 = 0; f0 < 512; f0 += 256) {
            int f = f0 + t;
            int row = f >> 3;             // 0..63
            int kpc = (f & 7) * 4;        // u32 col
            int cl = row >> 5;
            uint32_t* dh = Ah + row * GXM_PA + kpc;
            uint32_t* dm = Am + row * GXM_PA + kpc;
            if (cl == 0 || c1ok) {
                int srcoff = (row & 31) * 32 + kpc;
                CPA16(smem_u32(dh), srcs_h[cl] + srcoff);
                CPA16(smem_u32(dm), srcs_m[cl] + srcoff);
            } else {
                *(uint4*)dh = make_uint4(0u, 0u, 0u, 0u);
                *(uint4*)dm = make_uint4(0u, 0u, 0u, 0u);
            }
        }
        // W tiles: 32 kp x 384 g
        for (int f = t; f < 32 * 96; f += 256) {
            int kp = f / 96, c16 = (f % 96) * 4;
            size_t gsrc = ((size_t)d * 32 + kp) * Gg + c16;
            CPA16(smem_u32(Wh_s + kp * GXM_PW + c16), g_Wxh + gsrc);
            CPA16(smem_u32(Wm_s + kp * GXM_PW + c16), g_Wxm + gsrc);
        }
        for (int f = t; f < Gg / 4; f += 256) {
            CPA16(smem_u32(bs + f * 4), bias + (size_t)d * Gg + f * 4);
        }
        CPC(); CPW0();
        __syncthreads();
    }

    // ---- bf16x3 MMA: K=64 (4 k16 steps), warp covers 2 m16 x 12 n8 ----
    float acc[2][12][4];
#pragma unroll
    for (int mt = 0; mt < 2; mt++)
#pragma unroll
        for (int nn = 0; nn < 12; nn++)
#pragma unroll
            for (int v = 0; v < 4; v++) acc[mt][nn][v] = 0.f;

    const uint32_t* AhRow = Ah + (mp * 32 + gi) * GXM_PA;
    const uint32_t* AmRow = Am + (mp * 32 + gi) * GXM_PA;

#pragma unroll
    for (int k16 = 0; k16 < 4; k16++) {
        const int kp0 = k16 * 8;
        unsigned ahf[2][4], amf[2][4];
#pragma unroll
        for (int mt = 0; mt < 2; mt++) {
            const uint32_t* Ah0 = AhRow + mt * 16 * GXM_PA + kp0;
            const uint32_t* Am0 = AmRow + mt * 16 * GXM_PA + kp0;
            ahf[mt][0] = Ah0[ci];     ahf[mt][1] = Ah0[8 * GXM_PA + ci];
            ahf[mt][2] = Ah0[ci + 4]; ahf[mt][3] = Ah0[8 * GXM_PA + ci + 4];
            amf[mt][0] = Am0[ci];     amf[mt][1] = Am0[8 * GXM_PA + ci];
            amf[mt][2] = Am0[ci + 4]; amf[mt][3] = Am0[8 * GXM_PA + ci + 4];
        }
#pragma unroll
        for (int nn = 0; nn < 12; nn++) {
            const int c = ng * 96 + nn * 8 + gi;
            unsigned bh0 = Wh_s[(kp0 + ci) * GXM_PW + c];
            unsigned bh1 = Wh_s[(kp0 + ci + 4) * GXM_PW + c];
            unsigned bm0 = Wm_s[(kp0 + ci) * GXM_PW + c];
            unsigned bm1 = Wm_s[(kp0 + ci + 4) * GXM_PW + c];
#pragma unroll
            for (int mt = 0; mt < 2; mt++) {
                MMA_BF16(acc[mt][nn], ahf[mt][0], ahf[mt][1], ahf[mt][2], ahf[mt][3], bh0, bh1);
                MMA_BF16(acc[mt][nn], amf[mt][0], amf[mt][1], amf[mt][2], amf[mt][3], bh0, bh1);
                MMA_BF16(acc[mt][nn], ahf[mt][0], ahf[mt][1], ahf[mt][2], ahf[mt][3], bm0, bm1);
            }
        }
    }

    // ---- store: g_gx[cell][b][g] = acc + bias[g] ----
    if (!(mp == 1 && !c1ok)) {
        const size_t cell = (size_t)d * CELLS + (size_t)p * RR + (mp ? q1 : q0);
#pragma unroll
        for (int mt = 0; mt < 2; mt++) {
#pragma unroll
            for (int half = 0; half < 2; half++) {
                const int b = mt * 16 + half * 8 + gi;
                float* gp = g_gx + (cell * Bz + b) * Gg;
#pragma unroll
                for (int nn = 0; nn < 12; nn++) {
                    const int col = ng * 96 + nn * 8 + 2 * ci;
                    float2 v = make_float2(acc[mt][nn][half * 2 + 0] + bs[col],
                                           acc[mt][nn][half * 2 + 1] + bs[col + 1]);
                    *(float2*)(gp + col) = v;
                }
            }
        }
    }
}

// ---------------------------------------------------------------------------
// Persistent bf16x3 wavefront scan (unchanged from R12 WIN).
static constexpr int PAD_W = 104;
static constexpr int PAD_A = 132;
static constexpr int OFF_WPH = 0;
static constexpr int OFF_WPM = OFF_WPH + 128 * PAD_W;
static constexpr int OFF_AH  = OFF_WPM + 128 * PAD_W;
static constexpr int OFF_AM  = OFF_AH  + 64 * PAD_A;
static constexpr int SCAN_SMEM = (OFF_AM + 64 * PAD_A) * 4;   // 174080 B

__device__ __forceinline__ void grid_barrier_d(int d, int gen) {
    __syncthreads();
    if (threadIdx.x == 0) {
        __threadfence();
        if (atomicAdd(&g_bar_count[d], 1) == NCTA_D - 1) {
            g_bar_count[d] = 0;
            __threadfence();
            g_bar_gen[d] = gen;
        } else {
            while (g_bar_gen[d] < gen) { __nanosleep(32); }
            __threadfence();
        }
    }
    __syncthreads();
}

__global__ void __launch_bounds__(256, 1) scan_persist_kernel() {
    extern __shared__ uint32_t smu[];
    uint32_t* Wph_s = smu + OFF_WPH;
    uint32_t* Wpm_s = smu + OFF_WPM;
    uint32_t* Ah    = smu + OFF_AH;
    uint32_t* Am    = smu + OFF_AM;

    const int cta = blockIdx.x;
    const int d  = cta / 36;
    const int kq = (cta / 9) % 4;
    const int j  = cta % 9;
    const int t  = threadIdx.x;
    const int w = t >> 5, lane = t & 31;
    const int gi = lane >> 2, ci = lane & 3;
    const int mp = w >> 2;
    const int ng = w & 3;

    for (int idx = t; idx < 128 * 96; idx += 256) {
        int kp = idx / 96, c = idx % 96;
        int gcol = (c >> 5) * 128 + kq * 32 + (c & 31);
        size_t gsrc = ((size_t)d * 128 + kp) * Gg + gcol;
        Wph_s[kp * PAD_W + c] = g_Wph[gsrc];
        Wpm_s[kp * PAD_W + c] = g_Wpm[gsrc];
    }
    __syncthreads();

    for (int s = 0; s < 2 * RR - 1; s++) {
        const int qlo = (s - (RR - 1) > 0) ? (s - (RR - 1)) : 0;
        const int qhi = (s < RR - 1) ? s : (RR - 1);
        const int npairs = (qhi - qlo + 2) >> 1;

        for (int pi = j; pi < npairs; pi += 9) {
            const int q0 = qlo + 2 * pi;
            const int q1 = q0 + 1;
            const bool c1ok = (q1 <= qhi);
            const int p0 = s - q0;
            const int p1 = s - q1;
            const size_t cell0 = (size_t)d * CELLS + (size_t)p0 * RR + q0;
            const size_t cell1 = (size_t)d * CELLS + (size_t)p1 * RR + q1;

            {
#pragma unroll
                for (int f0 = 0; f0 < 2048; f0 += 256) {
                    const int f = f0 + t;
                    const int row = f >> 5;
                    const int c4  = (f & 31) * 4;
                    const int cIdx = row >> 5;
                    const int b = row & 31;
                    const bool isUp = (c4 < 64);
                    const int kloc = isUp ? c4 : (c4 - 64);
                    bool valid;
                    size_t srcCell;
                    if (cIdx == 0) {
                        valid = isUp ? (p0 > 0) : (q0 > 0);
                        srcCell = isUp ? (cell0 - RR) : (cell0 - 1);
                    } else {
                        valid = c1ok && (isUp ? (p1 > 0) : (q1 > 0));
                        srcCell = isUp ? (cell1 - RR) : (cell1 - 1);
                    }
                    uint32_t* dh = Ah + row * PAD_A + c4;
                    uint32_t* dm = Am + row * PAD_A + c4;
                    if (valid) {
                        size_t off = (srcCell * Bz + b) * 64 + kloc;
                        CPA16(smem_u32(dh), g_hph + off);
                        CPA16(smem_u32(dm), g_hpm + off);
                    } else {
                        *(uint4*)dh = make_uint4(0u, 0u, 0u, 0u);
                        *(uint4*)dm = make_uint4(0u, 0u, 0u, 0u);
                    }
                }
                CPC(); CPW0();
                __syncthreads();
            }

            float acc[2][3][4];
#pragma unroll
            for (int mt = 0; mt < 2; mt++)
#pragma unroll
                for (int g = 0; g < 3; g++)
#pragma unroll
                    for (int v = 0; v < 4; v++) acc[mt][g][v] = 0.f;

            const int cb0 = ng * 8 + gi;
            const uint32_t* AhRow = Ah + (mp * 32 + gi) * PAD_A;
            const uint32_t* AmRow = Am + (mp * 32 + gi) * PAD_A;

#pragma unroll 2
            for (int k16 = 0; k16 < 16; k16++) {
                const int kp0 = k16 * 8;
                unsigned bh[3][2], bm[3][2];
#pragma unroll
                for (int g = 0; g < 3; g++) {
                    const int c = g * 32 + cb0;
                    bh[g][0] = Wph_s[(kp0 + ci) * PAD_W + c];
                    bh[g][1] = Wph_s[(kp0 + ci + 4) * PAD_W + c];
                    bm[g][0] = Wpm_s[(kp0 + ci) * PAD_W + c];
                    bm[g][1] = Wpm_s[(kp0 + ci + 4) * PAD_W + c];
                }
#pragma unroll
                for (int mt = 0; mt < 2; mt++) {
                    const uint32_t* Ah0 = AhRow + mt * 16 * PAD_A + kp0;
                    const uint32_t* Am0 = AmRow + mt * 16 * PAD_A + kp0;
                    unsigned ah0 = Ah0[ci],           ah1 = Ah0[8 * PAD_A + ci];
                    unsigned ah2 = Ah0[ci + 4],       ah3 = Ah0[8 * PAD_A + ci + 4];
                    unsigned am0 = Am0[ci],           am1 = Am0[8 * PAD_A + ci];
                    unsigned am2 = Am0[ci + 4],       am3 = Am0[8 * PAD_A + ci + 4];
#pragma unroll
                    for (int g = 0; g < 3; g++) {
                        MMA_BF16(acc[mt][g], ah0, ah1, ah2, ah3, bh[g][0], bh[g][1]);
                        MMA_BF16(acc[mt][g], am0, am1, am2, am3, bh[g][0], bh[g][1]);
                        MMA_BF16(acc[mt][g], ah0, ah1, ah2, ah3, bm[g][0], bm[g][1]);
                    }
                }
            }

            if (!(mp == 1 && !c1ok)) {
                const size_t cell = mp ? cell1 : cell0;
                const int kbase = kq * 32 + ng * 8 + 2 * ci;
                const int kp = kbase >> 1;
#pragma unroll
                for (int mt = 0; mt < 2; mt++) {
#pragma unroll
                    for (int half = 0; half < 2; half++) {
                        const int b = mt * 16 + half * 8 + gi;
                        const int row = mp * 32 + b;
                        const float* gxc = g_gx + (cell * Bz + b) * Gg;
                        float2 gr = __ldcg((const float2*)(gxc + kbase));
                        float2 gz = __ldcg((const float2*)(gxc + 128 + kbase));
                        float2 gn = __ldcg((const float2*)(gxc + 256 + kbase));
                        uint32_t huH = Ah[row * PAD_A + kp];
                        uint32_t huM = Am[row * PAD_A + kp];
                        uint32_t hlH = Ah[row * PAD_A + 64 + kp];
                        uint32_t hlM = Am[row * PAD_A + 64 + kp];
                        float hu0 = bf_lo(huH) + bf_lo(huM);
                        float hu1 = bf_hi(huH) + bf_hi(huM);
                        float hl0 = bf_lo(hlH) + bf_lo(hlM);
                        float hl1 = bf_hi(hlH) + bf_hi(hlM);
                        float r0 = sigf(acc[mt][0][half * 2 + 0] + gr.x);
                        float r1 = sigf(acc[mt][0][half * 2 + 1] + gr.y);
                        float z0 = sigf(acc[mt][1][half * 2 + 0] + gz.x);
                        float z1 = sigf(acc[mt][1][half * 2 + 1] + gz.y);
                        float n0 = tanhf_fast(gn.x + r0 * acc[mt][2][half * 2 + 0]);
                        float n1 = tanhf_fast(gn.y + r1 * acc[mt][2][half * 2 + 1]);
                        float h0 = (1.f - z0) * n0 + z0 * 0.5f * (hu0 + hl0);
                        float h1 = (1.f - z1) * n1 + z1 * 0.5f * (hu1 + hl1);
                        uint32_t vh, vm;
                        split2(h0, h1, vh, vm);
                        size_t off = (cell * Bz + b) * 64 + kp;
                        g_hph[off] = vh;
                        g_hpm[off] = vm;
                    }
                }
            }
            __syncthreads();
        }

        grid_barrier_d(d, s + 1);
    }
}

// ---------------------------------------------------------------------------
// Post-scan scatter (unchanged from R12 WIN).
__global__ void __launch_bounds__(256) scatter_kernel(float* __restrict__ out) {
    __shared__ float sm[32][129];
    const int bx = blockIdx.x;
    const int b  = blockIdx.y;
    const int d  = blockIdx.z;
    const int p  = bx >> 1;
    const int qt = bx & 1;
    const int qb = qt * 32;
    const int nq = qt ? 31 : 32;
    const int t  = threadIdx.x;

    for (int idx = t; idx < nq * 64; idx += 256) {
        const int qi = idx >> 6;
        const int kp = idx & 63;
        const size_t cell = (size_t)d * CELLS + (size_t)p * RR + (qb + qi);
        const size_t off = (cell * Bz + b) * 64 + kp;
        uint32_t vh = g_hph[off];
        uint32_t vm = g_hpm[off];
        sm[qi][2 * kp]     = bf_lo(vh) + bf_lo(vm);
        sm[qi][2 * kp + 1] = bf_hi(vh) + bf_hi(vm);
    }
    __syncthreads();

    const int oi = (d & 1) ? (63 - p) : p;
    for (int idx = t; idx < 32 * 128; idx += 256) {
        const int k  = idx >> 5;
        const int qi = idx & 31;
        if (qi < nq) {
            const int q  = qb + qi;
            const int oj = (d & 2) ? (63 - q) : q;
            out[((size_t)(b * 128 + k) * 4 + d) * 4096 + (size_t)oi * 64 + oj]
                = sm[qi][k];
        }
    }
}

// ---------------------------------------------------------------------------
extern "C" void kernel_launch(void* const* d_in, const int* in_sizes, int n_in,
                              void* d_out, int out_size) {
    const float* x    = (const float*)d_in[0];
    const float* Wx   = (const float*)d_in[1];
    const float* Wh   = (const float*)d_in[2];
    const float* Wh2  = (const float*)d_in[3];
    const float* bias = (const float*)d_in[4];
    float* out = (float*)d_out;

    cudaFuncSetAttribute(gx_mma_kernel,
                         cudaFuncAttributeMaxDynamicSharedMemorySize, GXM_SMEM);
    cudaFuncSetAttribute(scan_persist_kernel,
                         cudaFuncAttributeMaxDynamicSharedMemorySize, SCAN_SMEM);

    // 1) independent prep
    int n4 = out_size / 4;
    fill_ones_kernel<<<(n4 + 255) / 256, 256>>>((float4*)d_out, n4);
    wsplit_kernel<<<768, 256>>>(Wh, Wh2);
    wxsplit_kernel<<<192, 256>>>(Wx);
    xsplit_kernel<<<4096, 256>>>(x);
    reset_kernel<<<1, 1>>>();

    // 2) gx via bf16x3 mma
    {
        dim3 grid(32, 63, 4);
        gx_mma_kernel<<<grid, 256, GXM_SMEM>>>(bias);
    }

    // 3) persistent bf16x3 wavefront scan
    scan_persist_kernel<<<NCTAS, 256, SCAN_SMEM>>>();

    // 4) coalesced transpose of h into the output layout
    {
        dim3 grid(126, 32, 4);
        scatter_kernel<<<grid, 256>>>(out);
    }
}